// round 14
// baseline (speedup 1.0000x reference)
#include <cuda_runtime.h>
#include <cuda_bf16.h>
#include <math.h>
#include <stdint.h>

#define Bb 16
#define Cc 256
#define Nn 4096

// ---------------------------------------------------------------------------
// Global scratch
// ---------------------------------------------------------------------------
__device__ float g_inv1[Bb * Cc];
__device__ float g_inv2[Bb * Cc];
__device__ __nv_bfloat16 g_X1[Bb * Cc * Nn];   // bf16(x1)
__device__ __nv_bfloat16 g_X2[Bb * Cc * Nn];   // bf16(x2)
__device__ float g_L1[Bb * Cc * Cc];           // logits1 (full K)
__device__ float g_L2[Bb * Cc * Cc];
__device__ __nv_bfloat16 g_A1[Bb * Cc * Cc];   // softmax bf16
__device__ __nv_bfloat16 g_A2[Bb * Cc * Cc];

// ---------------------------------------------------------------------------
// PTX helpers (portable sm_80-era only)
// ---------------------------------------------------------------------------
__device__ __forceinline__ uint32_t smem_u32(const void* p) {
    uint32_t a;
    asm("{ .reg .u64 t; cvta.to.shared.u64 t, %1; cvt.u32.u64 %0, t; }"
        : "=r"(a) : "l"(p));
    return a;
}

__device__ __forceinline__ void mma16816(float* d, const uint32_t* a, const uint32_t* b) {
    asm volatile("mma.sync.aligned.m16n8k16.row.col.f32.bf16.bf16.f32 "
        "{%0,%1,%2,%3}, {%4,%5,%6,%7}, {%8,%9}, {%0,%1,%2,%3};"
        : "+f"(d[0]), "+f"(d[1]), "+f"(d[2]), "+f"(d[3])
        : "r"(a[0]), "r"(a[1]), "r"(a[2]), "r"(a[3]), "r"(b[0]), "r"(b[1]));
}

__device__ __forceinline__ void ldsm4(uint32_t* r, uint32_t addr) {
    asm volatile("ldmatrix.sync.aligned.m8n8.x4.shared.b16 {%0,%1,%2,%3}, [%4];"
        : "=r"(r[0]), "=r"(r[1]), "=r"(r[2]), "=r"(r[3]) : "r"(addr));
}

__device__ __forceinline__ void ldsm4t(uint32_t* r, uint32_t addr) {
    asm volatile("ldmatrix.sync.aligned.m8n8.x4.trans.shared.b16 {%0,%1,%2,%3}, [%4];"
        : "=r"(r[0]), "=r"(r[1]), "=r"(r[2]), "=r"(r[3]) : "r"(addr));
}

#define CP16(dst, src) \
    asm volatile("cp.async.cg.shared.global [%0], [%1], 16;" \
        :: "r"(dst), "l"(src) : "memory")
#define CP_COMMIT() asm volatile("cp.async.commit_group;" ::: "memory")
#define CP_WAIT2()  asm volatile("cp.async.wait_group 2;"  ::: "memory")

// XOR swizzle for 128B-row tiles (chunk 0..7)
__device__ __forceinline__ uint32_t swz(int row, int chunk) {
    return (uint32_t)(row * 128 + ((chunk ^ (row & 7)) << 4));
}
// XOR swizzle for 64B-row tiles (chunk 0..3)
__device__ __forceinline__ uint32_t swz64(int row, int chunk) {
    return (uint32_t)(row * 64 + ((chunk ^ ((row >> 1) & 3)) << 4));
}

__device__ __forceinline__ uint32_t pk(float lo, float hi) {
    __nv_bfloat162 t = __floats2bfloat162_rn(lo, hi);
    return *reinterpret_cast<uint32_t*>(&t);
}

// combine two bf16x2 fragments with fp32 row scalars: out = a1*i1 + a2*i2
__device__ __forceinline__ uint32_t comb(uint32_t a1, uint32_t a2, float i1, float i2) {
    float a1lo = __uint_as_float(a1 << 16);
    float a1hi = __uint_as_float(a1 & 0xffff0000u);
    float a2lo = __uint_as_float(a2 << 16);
    float a2hi = __uint_as_float(a2 & 0xffff0000u);
    return pk(a1lo * i1 + a2lo * i2, a1hi * i1 + a2hi * i2);
}

// ---------------------------------------------------------------------------
// Kernel 1: norms + bf16 materialization (X1, X2 only; S is formed in gemm1)
// ---------------------------------------------------------------------------
__global__ __launch_bounds__(256) void k_prep(const float* __restrict__ x1,
                                              const float* __restrict__ x2) {
    __shared__ float sx1[Nn], sx2[Nn];
    const int row = blockIdx.x, tid = threadIdx.x;
    const float4* p1 = reinterpret_cast<const float4*>(x1) + (size_t)row * (Nn / 4);
    const float4* p2 = reinterpret_cast<const float4*>(x2) + (size_t)row * (Nn / 4);
    float s1 = 0.f, s2 = 0.f;
    #pragma unroll
    for (int i = 0; i < 4; i++) {
        float4 v = p1[tid + i * 256];
        float4 w = p2[tid + i * 256];
        *(float4*)&sx1[(tid + i * 256) * 4] = v;
        *(float4*)&sx2[(tid + i * 256) * 4] = w;
        s1 += v.x*v.x + v.y*v.y + v.z*v.z + v.w*v.w;
        s2 += w.x*w.x + w.y*w.y + w.z*w.z + w.w*w.w;
    }
    #pragma unroll
    for (int o = 16; o > 0; o >>= 1) {
        s1 += __shfl_down_sync(0xffffffffu, s1, o);
        s2 += __shfl_down_sync(0xffffffffu, s2, o);
    }
    __shared__ float sh1[8], sh2[8];
    if ((tid & 31) == 0) { sh1[tid >> 5] = s1; sh2[tid >> 5] = s2; }
    __syncthreads();
    if (tid == 0) {
        float t1 = 0.f, t2 = 0.f;
        #pragma unroll
        for (int i = 0; i < 8; i++) { t1 += sh1[i]; t2 += sh2[i]; }
        g_inv1[row] = 1.0f / fmaxf(sqrtf(t1), 1e-12f);
        g_inv2[row] = 1.0f / fmaxf(sqrtf(t2), 1e-12f);
    }
    uint4* oX1 = reinterpret_cast<uint4*>(g_X1 + (size_t)row * Nn);
    uint4* oX2 = reinterpret_cast<uint4*>(g_X2 + (size_t)row * Nn);
    #pragma unroll
    for (int i = 0; i < 2; i++) {
        int seg = tid + i * 256;                 // 8 elems each
        float4 a = *(const float4*)&sx1[seg * 8];
        float4 b = *(const float4*)&sx1[seg * 8 + 4];
        float4 c = *(const float4*)&sx2[seg * 8];
        float4 d = *(const float4*)&sx2[seg * 8 + 4];
        uint4 u1 = { pk(a.x, a.y), pk(a.z, a.w), pk(b.x, b.y), pk(b.z, b.w) };
        uint4 u2 = { pk(c.x, c.y), pk(c.z, c.w), pk(d.x, d.y), pk(d.z, d.w) };
        oX1[seg] = u1; oX2[seg] = u2;
    }
}

// ---------------------------------------------------------------------------
// Kernel 2: GEMM1, no split-K. CTA 64(c) x 64(d), K=4096, KT=32, 4 stages.
//   L1[c,d] = (sum_n S[c,n]*X1[d,n]) * inv1[d],  S combined in-register.
// Stage 16KB: X1c @0, X2c @4096, X1d @8192, X2d @12288 (64 rows x 64B each).
// 8 warps = 4(c, 16 rows) x 2(d, 32 cols). 128 K-iterations.
// ---------------------------------------------------------------------------
#define G1_STAGE 16384
#define G1_SMEM  (4 * G1_STAGE + 1024)

__global__ __launch_bounds__(256, 2) void k_gemm1() {
    extern __shared__ __align__(128) char smem[];
    const uint32_t sb = smem_u32(smem);
    const int tid = threadIdx.x, lane = tid & 31, wid = tid >> 5;
    const int wc = wid >> 1, wd = wid & 1;
    const int b = blockIdx.z, c0 = blockIdx.y * 64, d0 = blockIdx.x * 64;

    float* invc = (float*)(smem + 4 * G1_STAGE);          // [2][64]
    float* invd = (float*)(smem + 4 * G1_STAGE + 512);    // [2][64]
    if (tid < 64) {
        invc[tid]      = g_inv1[b * Cc + c0 + tid];
        invc[64 + tid] = g_inv2[b * Cc + c0 + tid];
        invd[tid]      = g_inv1[b * Cc + d0 + tid];
        invd[64 + tid] = g_inv2[b * Cc + d0 + tid];
    }

    const char* gX1c = (const char*)(g_X1 + (size_t)(b * Cc + c0) * Nn);
    const char* gX2c = (const char*)(g_X2 + (size_t)(b * Cc + c0) * Nn);
    const char* gX1d = (const char*)(g_X1 + (size_t)(b * Cc + d0) * Nn);
    const char* gX2d = (const char*)(g_X2 + (size_t)(b * Cc + d0) * Nn);

    // per stage: 4 sub-tiles x 64 rows x 4 chunks = 1024 chunks, 4/thread
    #define G1_LOAD(st, kt) do { \
        uint32_t s_ = sb + (uint32_t)(st) * G1_STAGE; \
        int r_ = tid >> 2, c_ = tid & 3; \
        size_t go_ = (size_t)r_ * 8192 + (size_t)(kt) * 64 + c_ * 16; \
        uint32_t so_ = swz64(r_, c_); \
        CP16(s_ + so_,         gX1c + go_); \
        CP16(s_ + 4096 + so_,  gX2c + go_); \
        CP16(s_ + 8192 + so_,  gX1d + go_); \
        CP16(s_ + 12288 + so_, gX2d + go_); \
    } while (0)

    G1_LOAD(0, 0); CP_COMMIT();
    G1_LOAD(1, 1); CP_COMMIT();
    G1_LOAD(2, 2); CP_COMMIT();
    __syncthreads();   // invc/invd visible

    // per-thread fp32 combine scalars (A-fragment rows)
    const int rA = wc * 16 + (lane >> 2);
    const float i1lo = invc[rA],     i2lo = invc[64 + rA];
    const float i1hi = invc[rA + 8], i2hi = invc[64 + rA + 8];

    float acc[2][4][4];
    #pragma unroll
    for (int o = 0; o < 2; o++)
        #pragma unroll
        for (int n = 0; n < 4; n++)
            #pragma unroll
            for (int k = 0; k < 4; k++) acc[o][n][k] = 0.f;

    for (int it = 0; it < 128; it++) {
        CP_WAIT2();
        __syncthreads();
        if (it + 3 < 128) G1_LOAD((it + 3) & 3, it + 3);
        CP_COMMIT();
        const uint32_t stg = sb + (uint32_t)(it & 3) * G1_STAGE;
        #pragma unroll
        for (int ks = 0; ks < 2; ks++) {
            const int ch = ks * 2 + (lane >> 4);
            // A: combine X1c, X2c fragments with fp32 row scalars
            uint32_t ra1[4], ra2[4], a[4];
            {
                int row = wc * 16 + (lane & 15);
                ldsm4(ra1, stg + swz64(row, ch));
                ldsm4(ra2, stg + 4096 + swz64(row, ch));
                a[0] = comb(ra1[0], ra2[0], i1lo, i2lo);
                a[1] = comb(ra1[1], ra2[1], i1hi, i2hi);
                a[2] = comb(ra1[2], ra2[2], i1lo, i2lo);
                a[3] = comb(ra1[3], ra2[3], i1hi, i2hi);
            }
            // B: raw X1d / X2d fragments
            uint32_t b1f[4][2], b2f[4][2], r4[4];
            #pragma unroll
            for (int p = 0; p < 2; p++) {
                int row = wd * 32 + p * 16 + (lane & 15);
                ldsm4(r4, stg + 8192 + swz64(row, ch));
                b1f[2*p][0] = r4[0]; b1f[2*p][1] = r4[2];
                b1f[2*p+1][0] = r4[1]; b1f[2*p+1][1] = r4[3];
                ldsm4(r4, stg + 12288 + swz64(row, ch));
                b2f[2*p][0] = r4[0]; b2f[2*p][1] = r4[2];
                b2f[2*p+1][0] = r4[1]; b2f[2*p+1][1] = r4[3];
            }
            #pragma unroll
            for (int nt = 0; nt < 4; nt++) {
                mma16816(acc[0][nt], a, b1f[nt]);
                mma16816(acc[1][nt], a, b2f[nt]);
            }
        }
    }

    // epilogue: scale by inv[d] (fp32), write full logits
    const int crow = b * Cc + c0 + wc * 16 + (lane >> 2);
    #pragma unroll
    for (int o = 0; o < 2; o++) {
        float* L = o ? g_L2 : g_L1;
        #pragma unroll
        for (int nt = 0; nt < 4; nt++) {
            int dl = wd * 32 + nt * 8 + (lane & 3) * 2;
            float s0 = invd[o * 64 + dl], s1 = invd[o * 64 + dl + 1];
            float* p = L + (size_t)crow * Cc + d0 + dl;
            *(float2*)p = make_float2(acc[o][nt][0] * s0, acc[o][nt][1] * s1);
            *(float2*)(p + 8 * Cc) = make_float2(acc[o][nt][2] * s0, acc[o][nt][3] * s1);
        }
    }
    #undef G1_LOAD
}

// ---------------------------------------------------------------------------
// Kernel 3: softmax(L) -> bf16 attn
// ---------------------------------------------------------------------------
__global__ __launch_bounds__(256) void k_softmax() {
    const int row = blockIdx.x, tid = threadIdx.x;
    const size_t idx = (size_t)row * Cc + tid;
    float v = blockIdx.y ? g_L2[idx] : g_L1[idx];
    __nv_bfloat16* A = (blockIdx.y ? g_A2 : g_A1) + (size_t)row * Cc;
    __shared__ float sh[8], bc;
    float m = v;
    #pragma unroll
    for (int o = 16; o > 0; o >>= 1) m = fmaxf(m, __shfl_xor_sync(0xffffffffu, m, o));
    if ((tid & 31) == 0) sh[tid >> 5] = m;
    __syncthreads();
    if (tid == 0) {
        float t = sh[0];
        #pragma unroll
        for (int i = 1; i < 8; i++) t = fmaxf(t, sh[i]);
        bc = t;
    }
    __syncthreads();
    float e = expf(v - bc);
    __syncthreads();
    float s = e;
    #pragma unroll
    for (int o = 16; o > 0; o >>= 1) s += __shfl_xor_sync(0xffffffffu, s, o);
    if ((tid & 31) == 0) sh[tid >> 5] = s;
    __syncthreads();
    if (tid == 0) {
        float t = 0.f;
        #pragma unroll
        for (int i = 0; i < 8; i++) t += sh[i];
        bc = t;
    }
    __syncthreads();
    A[tid] = __float2bfloat16(e / bc);
}

// ---------------------------------------------------------------------------
// Kernel 4: GEMM2 (round-6 form, best measured). CTA 128(q) x 64(n), K=256,
// KT=32, 4 stages (96KB), 8 iters, SMEM [n][q] restage epilogue.
// ---------------------------------------------------------------------------
#define G2_STAGE 24576
#define G2_SMEM  (4 * G2_STAGE)

__global__ __launch_bounds__(256, 2) void k_gemm2(const float* __restrict__ x1,
                                                  const float* __restrict__ x2,
                                                  float* __restrict__ out) {
    extern __shared__ __align__(128) char smem[];
    const uint32_t sb = smem_u32(smem);
    const int tid = threadIdx.x, lane = tid & 31, wid = tid >> 5;
    const int wq = wid >> 1, wn = wid & 1;
    const int b = blockIdx.z, q0 = blockIdx.y * 128, n0 = blockIdx.x * 64;

    const char* gA1 = (const char*)(g_A1 + (size_t)(b * Cc + q0) * Cc);
    const char* gA2 = (const char*)(g_A2 + (size_t)(b * Cc + q0) * Cc);
    const char* gX1 = (const char*)(g_X1 + (size_t)(b * Cc) * Nn) + (size_t)n0 * 2;
    const char* gX2 = (const char*)(g_X2 + (size_t)(b * Cc) * Nn) + (size_t)n0 * 2;

    #define G2_LOAD(st, kt) do { \
        uint32_t s_ = sb + (uint32_t)(st) * G2_STAGE; \
        _Pragma("unroll") \
        for (int i_ = 0; i_ < 2; i_++) { \
            int id_ = i_ * 256 + tid, r_ = id_ >> 2, c_ = id_ & 3; \
            size_t go_ = (size_t)r_ * 512 + (size_t)(kt) * 64 + c_ * 16; \
            CP16(s_ + swz64(r_, c_), gA1 + go_); \
            CP16(s_ + 8192 + swz64(r_, c_), gA2 + go_); \
        } \
        { \
            int r_ = tid >> 3, c_ = tid & 7; \
            size_t go_ = (size_t)((kt) * 32 + r_) * 8192 + c_ * 16; \
            CP16(s_ + 16384 + swz(r_, c_), gX1 + go_); \
            CP16(s_ + 20480 + swz(r_, c_), gX2 + go_); \
        } \
    } while (0)

    float acc[2][4][4];
    #pragma unroll
    for (int m = 0; m < 2; m++)
        #pragma unroll
        for (int n = 0; n < 4; n++)
            #pragma unroll
            for (int k = 0; k < 4; k++) acc[m][n][k] = 0.f;

    G2_LOAD(0, 0); CP_COMMIT();
    G2_LOAD(1, 1); CP_COMMIT();
    G2_LOAD(2, 2); CP_COMMIT();

    for (int it = 0; it < 8; it++) {
        CP_WAIT2();
        __syncthreads();
        if (it + 3 < 8) G2_LOAD((it + 3) & 3, it + 3);
        CP_COMMIT();
        const uint32_t stg = sb + (uint32_t)(it & 3) * G2_STAGE;
        #pragma unroll
        for (int ks = 0; ks < 2; ks++) {
            uint32_t a1[2][4], a2[2][4], bx1[4][2], bx2[4][2], r4[4];
            const int ch = ks * 2 + (lane >> 4);
            #pragma unroll
            for (int mt = 0; mt < 2; mt++) {
                int row = wq * 32 + mt * 16 + (lane & 15);
                ldsm4(a1[mt], stg + swz64(row, ch));
                ldsm4(a2[mt], stg + 8192 + swz64(row, ch));
            }
            #pragma unroll
            for (int p = 0; p < 2; p++) {
                int drow = ks * 16 + (lane & 15);
                int xch = 4 * wn + 2 * p + (lane >> 4);
                ldsm4t(r4, stg + 16384 + swz(drow, xch));
                bx1[2*p][0] = r4[0]; bx1[2*p][1] = r4[1];
                bx1[2*p+1][0] = r4[2]; bx1[2*p+1][1] = r4[3];
                ldsm4t(r4, stg + 20480 + swz(drow, xch));
                bx2[2*p][0] = r4[0]; bx2[2*p][1] = r4[1];
                bx2[2*p+1][0] = r4[2]; bx2[2*p+1][1] = r4[3];
            }
            #pragma unroll
            for (int mt = 0; mt < 2; mt++)
                #pragma unroll
                for (int nt = 0; nt < 4; nt++) {
                    mma16816(acc[mt][nt], a1[mt], bx1[nt]);
                    mma16816(acc[mt][nt], a2[mt], bx2[nt]);
                }
        }
    }
    __syncthreads();

    // Epilogue: restage [64 n][132 q] fp32, fused residual, coalesced out
    float* eps = (float*)smem;
    #pragma unroll
    for (int mt = 0; mt < 2; mt++)
        #pragma unroll
        for (int nt = 0; nt < 4; nt++) {
            int qL = wq * 32 + mt * 16 + (lane >> 2);
            int rn = wn * 32 + nt * 8 + (lane & 3) * 2;
            eps[rn * 132 + qL]           = acc[mt][nt][0];
            eps[(rn + 1) * 132 + qL]     = acc[mt][nt][1];
            eps[rn * 132 + qL + 8]       = acc[mt][nt][2];
            eps[(rn + 1) * 132 + qL + 8] = acc[mt][nt][3];
        }
    __syncthreads();
    #pragma unroll
    for (int i = 0; i < 8; i++) {
        int slot = tid + i * 256;                 // 0..2047
        int row = slot >> 5, qi = slot & 31;
        size_t idx = ((size_t)b << 20) + (size_t)(n0 + row) * 256 + q0 + qi * 4;
        float4 d4 = *(const float4*)&eps[row * 132 + qi * 4];
        float4 ra = *(const float4*)(x1 + idx);
        float4 rb = *(const float4*)(x2 + idx);
        d4.x += ra.x + rb.x; d4.y += ra.y + rb.y;
        d4.z += ra.z + rb.z; d4.w += ra.w + rb.w;
        *(float4*)(out + idx) = d4;
    }
    #undef G2_LOAD
}

// ---------------------------------------------------------------------------
extern "C" void kernel_launch(void* const* d_in, const int* in_sizes, int n_in,
                              void* d_out, int out_size) {
    const float* x1 = (const float*)d_in[0];
    const float* x2 = (const float*)d_in[1];
    float* out = (float*)d_out;

    cudaFuncSetAttribute(k_gemm1, cudaFuncAttributeMaxDynamicSharedMemorySize, G1_SMEM);
    cudaFuncSetAttribute(k_gemm2, cudaFuncAttributeMaxDynamicSharedMemorySize, G2_SMEM);

    k_prep<<<Bb * Cc, 256>>>(x1, x2);
    k_gemm1<<<dim3(4, 4, Bb), 256, G1_SMEM>>>();
    k_softmax<<<dim3(Bb * Cc, 2), 256>>>();
    k_gemm2<<<dim3(Nn / 64, 2, Bb), 256, G2_SMEM>>>(x1, x2, out);
}

// round 15
// speedup vs baseline: 1.2214x; 1.2214x over previous
#include <cuda_runtime.h>
#include <cuda_bf16.h>
#include <math.h>
#include <stdint.h>

#define Bb 16
#define Cc 256
#define Nn 4096

// ---------------------------------------------------------------------------
// Global scratch
// ---------------------------------------------------------------------------
__device__ float g_inv1[Bb * Cc];
__device__ float g_inv2[Bb * Cc];
__device__ __nv_bfloat16 g_S [Bb * Cc * Nn];   // s = x1*inv1 + x2*inv2
__device__ __nv_bfloat16 g_X1[Bb * Cc * Nn];   // bf16(x1)
__device__ __nv_bfloat16 g_X2[Bb * Cc * Nn];   // bf16(x2)
__device__ float g_L1 [Bb * Cc * Cc];          // logits1 partial (khalf 0)
__device__ float g_L2 [Bb * Cc * Cc];
__device__ float g_L1b[Bb * Cc * Cc];          // logits1 partial (khalf 1)
__device__ float g_L2b[Bb * Cc * Cc];
__device__ __nv_bfloat16 g_A1[Bb * Cc * Cc];   // softmax bf16
__device__ __nv_bfloat16 g_A2[Bb * Cc * Cc];

// ---------------------------------------------------------------------------
// PTX helpers (portable sm_80-era only)
// ---------------------------------------------------------------------------
__device__ __forceinline__ uint32_t smem_u32(const void* p) {
    uint32_t a;
    asm("{ .reg .u64 t; cvta.to.shared.u64 t, %1; cvt.u32.u64 %0, t; }"
        : "=r"(a) : "l"(p));
    return a;
}

__device__ __forceinline__ void mma16816(float* d, const uint32_t* a, const uint32_t* b) {
    asm volatile("mma.sync.aligned.m16n8k16.row.col.f32.bf16.bf16.f32 "
        "{%0,%1,%2,%3}, {%4,%5,%6,%7}, {%8,%9}, {%0,%1,%2,%3};"
        : "+f"(d[0]), "+f"(d[1]), "+f"(d[2]), "+f"(d[3])
        : "r"(a[0]), "r"(a[1]), "r"(a[2]), "r"(a[3]), "r"(b[0]), "r"(b[1]));
}

__device__ __forceinline__ void ldsm4(uint32_t* r, uint32_t addr) {
    asm volatile("ldmatrix.sync.aligned.m8n8.x4.shared.b16 {%0,%1,%2,%3}, [%4];"
        : "=r"(r[0]), "=r"(r[1]), "=r"(r[2]), "=r"(r[3]) : "r"(addr));
}

__device__ __forceinline__ void ldsm4t(uint32_t* r, uint32_t addr) {
    asm volatile("ldmatrix.sync.aligned.m8n8.x4.trans.shared.b16 {%0,%1,%2,%3}, [%4];"
        : "=r"(r[0]), "=r"(r[1]), "=r"(r[2]), "=r"(r[3]) : "r"(addr));
}

#define CP16(dst, src) \
    asm volatile("cp.async.cg.shared.global [%0], [%1], 16;" \
        :: "r"(dst), "l"(src) : "memory")
#define CP_COMMIT() asm volatile("cp.async.commit_group;" ::: "memory")
#define CP_WAIT2()  asm volatile("cp.async.wait_group 2;"  ::: "memory")

// XOR swizzle for 128B-row tiles (chunk 0..7)
__device__ __forceinline__ uint32_t swz(int row, int chunk) {
    return (uint32_t)(row * 128 + ((chunk ^ (row & 7)) << 4));
}
// XOR swizzle for 64B-row tiles (chunk 0..3)
__device__ __forceinline__ uint32_t swz64(int row, int chunk) {
    return (uint32_t)(row * 64 + ((chunk ^ ((row >> 1) & 3)) << 4));
}

__device__ __forceinline__ uint32_t pk(float lo, float hi) {
    __nv_bfloat162 t = __floats2bfloat162_rn(lo, hi);
    return *reinterpret_cast<uint32_t*>(&t);
}

// ---------------------------------------------------------------------------
// Kernel 1: norms + bf16 materialization (SMEM-staged single global read)
// ---------------------------------------------------------------------------
__global__ __launch_bounds__(256) void k_prep(const float* __restrict__ x1,
                                              const float* __restrict__ x2) {
    __shared__ float sx1[Nn], sx2[Nn];
    const int row = blockIdx.x, tid = threadIdx.x;
    const float4* p1 = reinterpret_cast<const float4*>(x1) + (size_t)row * (Nn / 4);
    const float4* p2 = reinterpret_cast<const float4*>(x2) + (size_t)row * (Nn / 4);
    float s1 = 0.f, s2 = 0.f;
    #pragma unroll
    for (int i = 0; i < 4; i++) {
        float4 v = p1[tid + i * 256];
        float4 w = p2[tid + i * 256];
        *(float4*)&sx1[(tid + i * 256) * 4] = v;
        *(float4*)&sx2[(tid + i * 256) * 4] = w;
        s1 += v.x*v.x + v.y*v.y + v.z*v.z + v.w*v.w;
        s2 += w.x*w.x + w.y*w.y + w.z*w.z + w.w*w.w;
    }
    #pragma unroll
    for (int o = 16; o > 0; o >>= 1) {
        s1 += __shfl_down_sync(0xffffffffu, s1, o);
        s2 += __shfl_down_sync(0xffffffffu, s2, o);
    }
    __shared__ float sh1[8], sh2[8], bi1, bi2;
    if ((tid & 31) == 0) { sh1[tid >> 5] = s1; sh2[tid >> 5] = s2; }
    __syncthreads();
    if (tid == 0) {
        float t1 = 0.f, t2 = 0.f;
        #pragma unroll
        for (int i = 0; i < 8; i++) { t1 += sh1[i]; t2 += sh2[i]; }
        bi1 = 1.0f / fmaxf(sqrtf(t1), 1e-12f);
        bi2 = 1.0f / fmaxf(sqrtf(t2), 1e-12f);
        g_inv1[row] = bi1; g_inv2[row] = bi2;
    }
    __syncthreads();
    const float i1 = bi1, i2 = bi2;
    uint4* oS  = reinterpret_cast<uint4*>(g_S  + (size_t)row * Nn);
    uint4* oX1 = reinterpret_cast<uint4*>(g_X1 + (size_t)row * Nn);
    uint4* oX2 = reinterpret_cast<uint4*>(g_X2 + (size_t)row * Nn);
    #pragma unroll
    for (int i = 0; i < 2; i++) {
        int seg = tid + i * 256;                 // 8 elems each
        float4 a = *(const float4*)&sx1[seg * 8];
        float4 b = *(const float4*)&sx1[seg * 8 + 4];
        float4 c = *(const float4*)&sx2[seg * 8];
        float4 d = *(const float4*)&sx2[seg * 8 + 4];
        uint4 u1 = { pk(a.x, a.y), pk(a.z, a.w), pk(b.x, b.y), pk(b.z, b.w) };
        uint4 u2 = { pk(c.x, c.y), pk(c.z, c.w), pk(d.x, d.y), pk(d.z, d.w) };
        uint4 us = { pk(a.x*i1 + c.x*i2, a.y*i1 + c.y*i2),
                     pk(a.z*i1 + c.z*i2, a.w*i1 + c.w*i2),
                     pk(b.x*i1 + d.x*i2, b.y*i1 + d.y*i2),
                     pk(b.z*i1 + d.z*i2, b.w*i1 + d.w*i2) };
        oX1[seg] = u1; oX2[seg] = u2; oS[seg] = us;
    }
}

// ---------------------------------------------------------------------------
// Kernel 2: GEMM1, split-K x2. CTA 128(c) x 64(d), K=2048 per half.
// KT=32, 4-stage cp.async pipeline (16KB/stage), 64 iterations.
// ---------------------------------------------------------------------------
#define G1_STAGE 16384
#define G1_SMEM  (4 * G1_STAGE + 512)

__global__ __launch_bounds__(256, 2) void k_gemm1() {
    extern __shared__ __align__(128) char smem[];
    const uint32_t sb = smem_u32(smem);
    const int tid = threadIdx.x, lane = tid & 31, wid = tid >> 5;
    const int wc = wid >> 1, wd = wid & 1;
    const int b = blockIdx.z, c0 = blockIdx.y * 128;
    const int d0 = (blockIdx.x >> 1) * 64, kh = blockIdx.x & 1;

    float* invs = (float*)(smem + 4 * G1_STAGE);
    if (tid < 64) {
        invs[tid]      = g_inv1[b * Cc + d0 + tid];
        invs[64 + tid] = g_inv2[b * Cc + d0 + tid];
    }

    const size_t kOff = (size_t)kh * 4096;
    const char* gS = (const char*)(g_S  + (size_t)(b * Cc + c0) * Nn) + kOff;
    const char* gU = (const char*)(g_X1 + (size_t)(b * Cc + d0) * Nn) + kOff;
    const char* gV = (const char*)(g_X2 + (size_t)(b * Cc + d0) * Nn) + kOff;

    #define G1_LOAD(st, kt) do { \
        uint32_t s_ = sb + (uint32_t)(st) * G1_STAGE; \
        _Pragma("unroll") \
        for (int i_ = 0; i_ < 2; i_++) { \
            int id_ = i_ * 256 + tid, r_ = id_ >> 2, c_ = id_ & 3; \
            CP16(s_ + swz64(r_, c_), gS + (size_t)r_ * 8192 + (size_t)(kt) * 64 + c_ * 16); \
        } \
        { \
            int r_ = tid >> 2, c_ = tid & 3; \
            CP16(s_ + 8192  + swz64(r_, c_), gU + (size_t)r_ * 8192 + (size_t)(kt) * 64 + c_ * 16); \
            CP16(s_ + 12288 + swz64(r_, c_), gV + (size_t)r_ * 8192 + (size_t)(kt) * 64 + c_ * 16); \
        } \
    } while (0)

    float acc[2][2][4][4];
    #pragma unroll
    for (int o = 0; o < 2; o++)
        #pragma unroll
        for (int m = 0; m < 2; m++)
            #pragma unroll
            for (int n = 0; n < 4; n++)
                #pragma unroll
                for (int k = 0; k < 4; k++) acc[o][m][n][k] = 0.f;

    G1_LOAD(0, 0); CP_COMMIT();
    G1_LOAD(1, 1); CP_COMMIT();
    G1_LOAD(2, 2); CP_COMMIT();

    for (int it = 0; it < 64; it++) {
        CP_WAIT2();
        __syncthreads();
        if (it + 3 < 64) G1_LOAD((it + 3) & 3, it + 3);
        CP_COMMIT();
        const uint32_t stg = sb + (uint32_t)(it & 3) * G1_STAGE;
        #pragma unroll
        for (int ks = 0; ks < 2; ks++) {
            uint32_t a[2][4], b1f[4][2], b2f[4][2], r4[4];
            const int ch = ks * 2 + (lane >> 4);
            #pragma unroll
            for (int mt = 0; mt < 2; mt++) {
                int row = wc * 32 + mt * 16 + (lane & 15);
                ldsm4(a[mt], stg + swz64(row, ch));
            }
            #pragma unroll
            for (int p = 0; p < 2; p++) {
                int row = wd * 32 + p * 16 + (lane & 15);
                ldsm4(r4, stg + 8192 + swz64(row, ch));
                b1f[2*p][0] = r4[0]; b1f[2*p][1] = r4[2];
                b1f[2*p+1][0] = r4[1]; b1f[2*p+1][1] = r4[3];
                ldsm4(r4, stg + 12288 + swz64(row, ch));
                b2f[2*p][0] = r4[0]; b2f[2*p][1] = r4[2];
                b2f[2*p+1][0] = r4[1]; b2f[2*p+1][1] = r4[3];
            }
            #pragma unroll
            for (int mt = 0; mt < 2; mt++)
                #pragma unroll
                for (int nt = 0; nt < 4; nt++) {
                    mma16816(acc[0][mt][nt], a[mt], b1f[nt]);
                    mma16816(acc[1][mt][nt], a[mt], b2f[nt]);
                }
        }
    }

    const int crow = b * Cc + c0 + wc * 32 + (lane >> 2);
    #pragma unroll
    for (int o = 0; o < 2; o++) {
        float* L = o ? (kh ? g_L2b : g_L2) : (kh ? g_L1b : g_L1);
        #pragma unroll
        for (int mt = 0; mt < 2; mt++)
            #pragma unroll
            for (int nt = 0; nt < 4; nt++) {
                int dl = wd * 32 + nt * 8 + (lane & 3) * 2;
                float s0 = invs[o * 64 + dl], s1 = invs[o * 64 + dl + 1];
                float* p = L + (size_t)(crow + mt * 16) * Cc + d0 + dl;
                *(float2*)p = make_float2(acc[o][mt][nt][0] * s0, acc[o][mt][nt][1] * s1);
                *(float2*)(p + 8 * Cc) = make_float2(acc[o][mt][nt][2] * s0, acc[o][mt][nt][3] * s1);
            }
    }
    #undef G1_LOAD
}

// ---------------------------------------------------------------------------
// Kernel 3: softmax( L + Lb ) -> bf16 attn
// ---------------------------------------------------------------------------
__global__ __launch_bounds__(256) void k_softmax() {
    const int row = blockIdx.x, tid = threadIdx.x;
    const size_t idx = (size_t)row * Cc + tid;
    float v = blockIdx.y ? (g_L2[idx] + g_L2b[idx]) : (g_L1[idx] + g_L1b[idx]);
    __nv_bfloat16* A = (blockIdx.y ? g_A2 : g_A1) + (size_t)row * Cc;
    __shared__ float sh[8], bc;
    float m = v;
    #pragma unroll
    for (int o = 16; o > 0; o >>= 1) m = fmaxf(m, __shfl_xor_sync(0xffffffffu, m, o));
    if ((tid & 31) == 0) sh[tid >> 5] = m;
    __syncthreads();
    if (tid == 0) {
        float t = sh[0];
        #pragma unroll
        for (int i = 1; i < 8; i++) t = fmaxf(t, sh[i]);
        bc = t;
    }
    __syncthreads();
    float e = expf(v - bc);
    __syncthreads();
    float s = e;
    #pragma unroll
    for (int o = 16; o > 0; o >>= 1) s += __shfl_xor_sync(0xffffffffu, s, o);
    if ((tid & 31) == 0) sh[tid >> 5] = s;
    __syncthreads();
    if (tid == 0) {
        float t = 0.f;
        #pragma unroll
        for (int i = 0; i < 8; i++) t += sh[i];
        bc = t;
    }
    __syncthreads();
    A[tid] = __float2bfloat16(e / bc);
}

// ---------------------------------------------------------------------------
// Kernel 4: GEMM2. CTA 128(q) x 64(n), K=256, KT=32, 4 stages (96KB), 8 iters.
// NEW: residual x1/x2 tiles are L2-prefetched right after the initial stage
// loads, so their 128MB of DRAM traffic overlaps the mainloop and the
// epilogue's LDGs hit L2. No smem, no sync, no cp.async-group interference.
// ---------------------------------------------------------------------------
#define G2_STAGE 24576
#define G2_SMEM  (4 * G2_STAGE)

__global__ __launch_bounds__(256, 2) void k_gemm2(const float* __restrict__ x1,
                                                  const float* __restrict__ x2,
                                                  float* __restrict__ out) {
    extern __shared__ __align__(128) char smem[];
    const uint32_t sb = smem_u32(smem);
    const int tid = threadIdx.x, lane = tid & 31, wid = tid >> 5;
    const int wq = wid >> 1, wn = wid & 1;
    const int b = blockIdx.z, q0 = blockIdx.y * 128, n0 = blockIdx.x * 64;

    const char* gA1 = (const char*)(g_A1 + (size_t)(b * Cc + q0) * Cc);
    const char* gA2 = (const char*)(g_A2 + (size_t)(b * Cc + q0) * Cc);
    const char* gX1 = (const char*)(g_X1 + (size_t)(b * Cc) * Nn) + (size_t)n0 * 2;
    const char* gX2 = (const char*)(g_X2 + (size_t)(b * Cc) * Nn) + (size_t)n0 * 2;

    #define G2_LOAD(st, kt) do { \
        uint32_t s_ = sb + (uint32_t)(st) * G2_STAGE; \
        _Pragma("unroll") \
        for (int i_ = 0; i_ < 2; i_++) { \
            int id_ = i_ * 256 + tid, r_ = id_ >> 2, c_ = id_ & 3; \
            size_t go_ = (size_t)r_ * 512 + (size_t)(kt) * 64 + c_ * 16; \
            CP16(s_ + swz64(r_, c_), gA1 + go_); \
            CP16(s_ + 8192 + swz64(r_, c_), gA2 + go_); \
        } \
        { \
            int r_ = tid >> 3, c_ = tid & 7; \
            size_t go_ = (size_t)((kt) * 32 + r_) * 8192 + c_ * 16; \
            CP16(s_ + 16384 + swz(r_, c_), gX1 + go_); \
            CP16(s_ + 20480 + swz(r_, c_), gX2 + go_); \
        } \
    } while (0)

    float acc[2][4][4];
    #pragma unroll
    for (int m = 0; m < 2; m++)
        #pragma unroll
        for (int n = 0; n < 4; n++)
            #pragma unroll
            for (int k = 0; k < 4; k++) acc[m][n][k] = 0.f;

    G2_LOAD(0, 0); CP_COMMIT();
    G2_LOAD(1, 1); CP_COMMIT();
    G2_LOAD(2, 2); CP_COMMIT();

    // L2-prefetch the residual tile: 64 n-rows x 512B per array = 512 lines.
    // id 0..511: arr = id&1, lid = id>>1; row = lid>>2, line-in-row = lid&3.
    #pragma unroll
    for (int j = 0; j < 2; j++) {
        int id = j * 256 + tid;
        int arr = id & 1, lid = id >> 1;
        int row = lid >> 2, lw = lid & 3;
        const char* p = (const char*)((arr ? x2 : x1)
            + (((size_t)b << 20) + (size_t)(n0 + row) * 256 + q0)) + lw * 128;
        asm volatile("prefetch.global.L2 [%0];" :: "l"(p));
    }

    for (int it = 0; it < 8; it++) {
        CP_WAIT2();
        __syncthreads();
        if (it + 3 < 8) G2_LOAD((it + 3) & 3, it + 3);
        CP_COMMIT();
        const uint32_t stg = sb + (uint32_t)(it & 3) * G2_STAGE;
        #pragma unroll
        for (int ks = 0; ks < 2; ks++) {
            uint32_t a1[2][4], a2[2][4], bx1[4][2], bx2[4][2], r4[4];
            const int ch = ks * 2 + (lane >> 4);
            #pragma unroll
            for (int mt = 0; mt < 2; mt++) {
                int row = wq * 32 + mt * 16 + (lane & 15);
                ldsm4(a1[mt], stg + swz64(row, ch));
                ldsm4(a2[mt], stg + 8192 + swz64(row, ch));
            }
            #pragma unroll
            for (int p = 0; p < 2; p++) {
                int drow = ks * 16 + (lane & 15);
                int xch = 4 * wn + 2 * p + (lane >> 4);
                ldsm4t(r4, stg + 16384 + swz(drow, xch));
                bx1[2*p][0] = r4[0]; bx1[2*p][1] = r4[1];
                bx1[2*p+1][0] = r4[2]; bx1[2*p+1][1] = r4[3];
                ldsm4t(r4, stg + 20480 + swz(drow, xch));
                bx2[2*p][0] = r4[0]; bx2[2*p][1] = r4[1];
                bx2[2*p+1][0] = r4[2]; bx2[2*p+1][1] = r4[3];
            }
            #pragma unroll
            for (int mt = 0; mt < 2; mt++)
                #pragma unroll
                for (int nt = 0; nt < 4; nt++) {
                    mma16816(acc[mt][nt], a1[mt], bx1[nt]);
                    mma16816(acc[mt][nt], a2[mt], bx2[nt]);
                }
        }
    }
    __syncthreads();

    // Epilogue: restage [64 n][132 q] fp32, fused residual (L2-hot), coalesced
    float* eps = (float*)smem;
    #pragma unroll
    for (int mt = 0; mt < 2; mt++)
        #pragma unroll
        for (int nt = 0; nt < 4; nt++) {
            int qL = wq * 32 + mt * 16 + (lane >> 2);
            int rn = wn * 32 + nt * 8 + (lane & 3) * 2;
            eps[rn * 132 + qL]           = acc[mt][nt][0];
            eps[(rn + 1) * 132 + qL]     = acc[mt][nt][1];
            eps[rn * 132 + qL + 8]       = acc[mt][nt][2];
            eps[(rn + 1) * 132 + qL + 8] = acc[mt][nt][3];
        }
    __syncthreads();
    #pragma unroll
    for (int h = 0; h < 2; h++) {
        float4 ra[4], rb[4], dv[4];
        #pragma unroll
        for (int i = 0; i < 4; i++) {
            int slot = tid + (h * 4 + i) * 256;       // 0..2047
            int row = slot >> 5, qi = slot & 31;
            size_t idx = ((size_t)b << 20) + (size_t)(n0 + row) * 256 + q0 + qi * 4;
            ra[i] = *(const float4*)(x1 + idx);
            rb[i] = *(const float4*)(x2 + idx);
            dv[i] = *(const float4*)&eps[row * 132 + qi * 4];
        }
        #pragma unroll
        for (int i = 0; i < 4; i++) {
            int slot = tid + (h * 4 + i) * 256;
            int row = slot >> 5, qi = slot & 31;
            size_t idx = ((size_t)b << 20) + (size_t)(n0 + row) * 256 + q0 + qi * 4;
            float4 o;
            o.x = dv[i].x + ra[i].x + rb[i].x;
            o.y = dv[i].y + ra[i].y + rb[i].y;
            o.z = dv[i].z + ra[i].z + rb[i].z;
            o.w = dv[i].w + ra[i].w + rb[i].w;
            *(float4*)(out + idx) = o;
        }
    }
    #undef G2_LOAD
}

// ---------------------------------------------------------------------------
extern "C" void kernel_launch(void* const* d_in, const int* in_sizes, int n_in,
                              void* d_out, int out_size) {
    const float* x1 = (const float*)d_in[0];
    const float* x2 = (const float*)d_in[1];
    float* out = (float*)d_out;

    cudaFuncSetAttribute(k_gemm1, cudaFuncAttributeMaxDynamicSharedMemorySize, G1_SMEM);
    cudaFuncSetAttribute(k_gemm2, cudaFuncAttributeMaxDynamicSharedMemorySize, G2_SMEM);

    k_prep<<<Bb * Cc, 256>>>(x1, x2);
    k_gemm1<<<dim3(8, 2, Bb), 256, G1_SMEM>>>();
    k_softmax<<<dim3(Bb * Cc, 2), 256>>>();
    k_gemm2<<<dim3(Nn / 64, 2, Bb), 256, G2_SMEM>>>(x1, x2, out);
}